// round 8
// baseline (speedup 1.0000x reference)
#include <cuda_runtime.h>
#include <math.h>

#define HID     512
#define EMB     512
#define VOCAB   31
#define T_ENC   16384
#define MAX_LEN 100
#define EOS_IDX 29

#define NB      148                // CTAs (== wave-1 capacity, 1 CTA/SM)
#define NT      512                // threads per CTA (16 warps)
#define NWARPS  (NB * 16)          // 2368 warps in fused phase

// ---------------- device state ------------------------------------------------
__device__ float    g_hbuf[2][HID];          // double-buffered hidden state
__device__ float    g_y[EMB];                // fed-back embedding
__device__ float    g_partU[NB * HID];
__device__ float    g_partZ[NB];
__device__ float    g_Z[MAX_LEN];
__device__ int      g_best[MAX_LEN];
__device__ float    g_attn_scratch[T_ENC];   // fallback attn target
__device__ unsigned g_count = 0;             // barrier arrive counter
__device__ unsigned g_gen   = 0;             // barrier generation

// ---------------- software grid barrier ----------------------------------------
// Canonical sense-free barrier: read gen fresh, arrive, last resets+bumps,
// others spin. gpu-scope fences give release/acquire (CCTL.IVALL on sm_103a).
__device__ __forceinline__ void grid_bar() {
    __syncthreads();
    if (threadIdx.x == 0) {
        __threadfence();
        unsigned gen = *(volatile unsigned*)&g_gen;   // before own arrive => pre-release value
        if (atomicAdd(&g_count, 1) == NB - 1) {
            atomicExch(&g_count, 0);
            __threadfence();
            atomicExch(&g_gen, gen + 1);
        } else {
            while (*(volatile unsigned*)&g_gen == gen) { }
        }
        __threadfence();
    }
    __syncthreads();
}

// ---------------- the whole decoder --------------------------------------------
__global__ void __launch_bounds__(NT, 1)
k_decode(const float* __restrict__ enc,   const float* __restrict__ embed,
         const float* __restrict__ w_ih,  const float* __restrict__ w_hh,
         const float* __restrict__ b_ih,  const float* __restrict__ b_hh,
         const float* __restrict__ w_out, const float* __restrict__ b_out,
         float* __restrict__ attn_out, long long attn_stride,
         float* __restrict__ out_logits, float* __restrict__ out_len)
{
    __shared__ __align__(16) float4 sx[EMB / 4];     // GRU: y
    __shared__ __align__(16) float4 shv[HID / 4];    // GRU: h
    __shared__ float  sg[8][3];                      // GRU gate partials
    __shared__ __align__(16) float4 sh4[128];        // fused: hnew
    __shared__ __align__(16) float  su[16][512];     // fused per-warp U partials
    __shared__ float  szw[16];
    __shared__ __align__(16) float  scat[1024];      // final: [summary|hnew]
    __shared__ float  slog[32];
    __shared__ float  szr[NB];
    __shared__ float  sZb;
    __shared__ int    sbest;
    __shared__ int    sflag;
    __shared__ unsigned sgen;

    const int tid = threadIdx.x, wid = tid >> 5, lane = tid & 31, cta = blockIdx.x;
    const float scale = 0.04419417382415922f;        // 1/sqrt(512)

    // ---- init: h=0, y=embed[EOS] ----
    if (cta == 0) { g_hbuf[0][tid] = 0.f; g_y[tid] = embed[EOS_IDX * EMB + tid]; }
    grid_bar();

    for (int step = 0; step < MAX_LEN; step++) {
        const int p  = step & 1;       // read hbuf[p]
        const int pn = p ^ 1;          // write hbuf[pn]

        // ================= phase 1: GRU (CTAs 0..127) =================
        if (cta < 128) {
            if (tid < 128)       sx[tid]        = ((const float4*)g_y)[tid];
            else if (tid < 256)  shv[tid - 128] = ((const float4*)g_hbuf[p])[tid - 128];
            __syncthreads();
            if (wid < 8) {
                int j = cta * 4 + (wid & 3);
                bool is_hh = wid >= 4;
                const float*  W  = is_hh ? w_hh : w_ih;
                const float4* sv = is_hh ? shv : sx;
                const float4* wr = (const float4*)(W + (size_t)j * 512);
                const float4* wz = (const float4*)(W + (size_t)(512 + j) * 512);
                const float4* wn = (const float4*)(W + (size_t)(1024 + j) * 512);
                float gr = 0.f, gz = 0.f, gn = 0.f;
#pragma unroll
                for (int i = 0; i < 4; i++) {
                    int k = lane + 32 * i;
                    float4 x4 = sv[k], a;
                    a = wr[k]; gr += a.x * x4.x + a.y * x4.y + a.z * x4.z + a.w * x4.w;
                    a = wz[k]; gz += a.x * x4.x + a.y * x4.y + a.z * x4.z + a.w * x4.w;
                    a = wn[k]; gn += a.x * x4.x + a.y * x4.y + a.z * x4.z + a.w * x4.w;
                }
#pragma unroll
                for (int o = 16; o > 0; o >>= 1) {
                    gr += __shfl_xor_sync(~0u, gr, o);
                    gz += __shfl_xor_sync(~0u, gz, o);
                    gn += __shfl_xor_sync(~0u, gn, o);
                }
                if (lane == 0) { sg[wid][0] = gr; sg[wid][1] = gz; sg[wid][2] = gn; }
            }
            __syncthreads();
            if (tid < 4) {
                int jj = cta * 4 + tid;
                float ar = (sg[tid][0] + b_ih[jj])        + (sg[tid + 4][0] + b_hh[jj]);
                float az = (sg[tid][1] + b_ih[512 + jj])  + (sg[tid + 4][1] + b_hh[512 + jj]);
                float xn =  sg[tid][2] + b_ih[1024 + jj];
                float hn =  sg[tid + 4][2] + b_hh[1024 + jj];
                float r = 1.f / (1.f + expf(-ar));
                float z = 1.f / (1.f + expf(-az));
                float n = tanhf(xn + r * hn);
                g_hbuf[pn][jj] = (1.f - z) * n + z * g_hbuf[p][jj];
            }
        }
        grid_bar();

        // ================= phase 2: fused scores+exp+Z+sum(e*v) =================
        if (tid < 128) sh4[tid] = ((const float4*)g_hbuf[pn])[tid];
        __syncthreads();

        float* arow = attn_out + (size_t)step * attn_stride;
        int gw = cta * 16 + wid;
        float4 u0 = make_float4(0.f, 0.f, 0.f, 0.f);
        float4 u1 = u0, u2 = u0, u3 = u0;
        float zacc = 0.f;

        for (int t = gw; t < T_ENC; t += NWARPS) {
            const float4* row = (const float4*)(enc + (size_t)t * 1024);
            float s = 0.f;
#pragma unroll
            for (int i = 0; i < 4; i++) {
                int k = lane + 32 * i;
                float4 a = row[k], h = sh4[k];
                s += a.x * h.x + a.y * h.y + a.z * h.z + a.w * h.w;
            }
#pragma unroll
            for (int o = 16; o > 0; o >>= 1) s += __shfl_xor_sync(~0u, s, o);
            float e = expf(s * scale);          // scores bounded (|h|<1) -> no max pass
            if (lane == 0) arow[t] = e;         // unnormalized; /Z at the end
            zacc += e;
            float4 v;
            v = row[128 + lane]; u0.x += e * v.x; u0.y += e * v.y; u0.z += e * v.z; u0.w += e * v.w;
            v = row[160 + lane]; u1.x += e * v.x; u1.y += e * v.y; u1.z += e * v.z; u1.w += e * v.w;
            v = row[192 + lane]; u2.x += e * v.x; u2.y += e * v.y; u2.z += e * v.z; u2.w += e * v.w;
            v = row[224 + lane]; u3.x += e * v.x; u3.y += e * v.y; u3.z += e * v.z; u3.w += e * v.w;
        }
        ((float4*)&su[wid][4 * lane])[0]       = u0;
        ((float4*)&su[wid][128 + 4 * lane])[0] = u1;
        ((float4*)&su[wid][256 + 4 * lane])[0] = u2;
        ((float4*)&su[wid][384 + 4 * lane])[0] = u3;
        if (lane == 0) szw[wid] = zacc;
        __syncthreads();
        {
            float s2 = su[0][tid];
#pragma unroll
            for (int w = 1; w < 16; w++) s2 += su[w][tid];
            g_partU[cta * 512 + tid] = s2;
        }
        if (tid == 0) {
            float s2 = szw[0];
#pragma unroll
            for (int w = 1; w < 16; w++) s2 += szw[w];
            g_partZ[cta] = s2;
        }
        __syncthreads();

        // ================= elect: last CTA to finish runs finalize =================
        if (tid == 0) {
            __threadfence();                                   // release our partials
            sgen  = *(volatile unsigned*)&g_gen;
            int last = (atomicAdd(&g_count, 1) == NB - 1);
            sflag = last;
            if (last) { atomicExch(&g_count, 0); __threadfence(); }  // acquire all partials
        }
        __syncthreads();

        if (sflag) {
            // ---- finalize (this CTA only) ----
            if (tid < NB) szr[tid] = g_partZ[tid];
            __syncthreads();
            if (tid == 0) {
                float z = 0.f;
#pragma unroll
                for (int g = 0; g < NB; g++) z += szr[g];      // fixed order
                sZb = z; g_Z[step] = z;
            }
            __syncthreads();
            float Z = sZb;
            {
                float u = 0.f;
#pragma unroll 4
                for (int b = 0; b < NB; b++) u += g_partU[b * 512 + tid];  // coalesced
                scat[tid]       = u / Z;
                scat[512 + tid] = g_hbuf[pn][tid];
            }
            __syncthreads();
#pragma unroll
            for (int rr = 0; rr < 2; rr++) {
                int rowi = wid + 16 * rr;
                if (rowi < VOCAB) {
                    const float4* wp = (const float4*)(w_out + (size_t)rowi * 1024);
                    float s = 0.f;
#pragma unroll
                    for (int i = 0; i < 8; i++) {
                        int k = lane + 32 * i;
                        float4 a = wp[k];
                        float4 c = ((const float4*)scat)[k];
                        s += a.x * c.x + a.y * c.y + a.z * c.z + a.w * c.w;
                    }
#pragma unroll
                    for (int o = 16; o > 0; o >>= 1) s += __shfl_xor_sync(~0u, s, o);
                    if (lane == 0) {
                        s += b_out[rowi];
                        if (out_logits) out_logits[(size_t)step * VOCAB + rowi] = s;
                        slog[rowi] = s;
                    }
                }
            }
            __syncthreads();
            if (tid == 0) {
                float bv = slog[0]; int bi = 0;
                for (int v = 1; v < VOCAB; v++)
                    if (slog[v] > bv) { bv = slog[v]; bi = v; }  // first-max (jnp.argmax)
                g_best[step] = bi; sbest = bi;
            }
            __syncthreads();
            g_y[tid] = embed[(size_t)sbest * EMB + tid];
            __syncthreads();
            if (tid == 0) { __threadfence(); atomicExch(&g_gen, sgen + 1); }  // release step
        } else {
            if (tid == 0) {
                while (*(volatile unsigned*)&g_gen == sgen) { }
                __threadfence();                                // acquire g_y/hnew/g_Z
            }
            __syncthreads();
        }
    }

    // ================= epilogue: normalize attn + length =================
    if (attn_stride) {
        const long long N = (long long)MAX_LEN * T_ENC;
        for (long long i = (long long)cta * NT + tid; i < N; i += (long long)NB * NT)
            attn_out[i] = attn_out[i] / g_Z[i >> 14];
    }
    if (cta == 0 && tid == 0 && out_len) {
        int len = MAX_LEN;
        for (int i = 0; i < MAX_LEN; i++)
            if (g_best[i] == EOS_IDX) { len = i; break; }
        *out_len = (float)len;
    }
}

// ---------------------------------------------------------------------------------
extern "C" void kernel_launch(void* const* d_in, const int* in_sizes, int n_in,
                              void* d_out, int out_size) {
    const float* enc   = (const float*)d_in[0];
    const float* embed = (const float*)d_in[2];
    const float* w_ih  = (const float*)d_in[3];
    const float* w_hh  = (const float*)d_in[4];
    const float* b_ih  = (const float*)d_in[5];
    const float* b_hh  = (const float*)d_in[6];
    const float* w_out = (const float*)d_in[7];
    const float* b_out = (const float*)d_in[8];

    float* outF = (float*)d_out;
    const long long N_LOG  = (long long)MAX_LEN * VOCAB;        // 3100
    const long long N_ATTN = (long long)MAX_LEN * T_ENC;        // 1638400

    float* out_logits = outF;
    float* out_len    = nullptr;
    float* out_attn   = nullptr;
    if ((long long)out_size >= N_LOG + 1 + N_ATTN) {            // logits | len | attn
        out_len  = outF + N_LOG;
        out_attn = outF + N_LOG + 1;
    } else if ((long long)out_size >= N_LOG + N_ATTN) {
        out_attn = outF + N_LOG;
    } else if ((long long)out_size == N_ATTN) {
        out_attn = outF;
        out_logits = nullptr;
    }

    float* attn_target = out_attn;
    long long attn_stride = T_ENC;
    if (!out_attn) {                                            // fallback scratch
        cudaGetSymbolAddress((void**)&attn_target, g_attn_scratch);
        attn_stride = 0;
    }

    k_decode<<<NB, NT>>>(enc, embed, w_ih, w_hh, b_ih, b_hh, w_out, b_out,
                         attn_target, attn_stride, out_logits, out_len);
}

// round 9
// speedup vs baseline: 1.7230x; 1.7230x over previous
#include <cuda_runtime.h>
#include <math.h>

#define HID     512
#define EMB     512
#define VOCAB   31
#define T_ENC   16384
#define MAX_LEN 100
#define EOS_IDX 29

#define NB_F    148                 // fused CTAs (one wave)
#define NT_F    512                 // threads (16 warps)
#define NWARPS  (NB_F * 16)         // 2368 warps

// ---------------- device state -------------------------------------------------
__device__ float    g_h[HID];
__device__ float    g_y[EMB];
__device__ float    g_hnew[HID];
__device__ float    g_partU[NB_F * HID];
__device__ float    g_partZ[NB_F];
__device__ float    g_Z[MAX_LEN];
__device__ int      g_best[MAX_LEN];
__device__ float    g_attn_scratch[T_ENC];
__device__ unsigned g_count = 0;

// ---------------- init -----------------------------------------------------------
__global__ void k_init(const float* __restrict__ embed) {
    int i = threadIdx.x;               // 512
    g_h[i] = 0.f;
    g_y[i] = embed[EOS_IDX * EMB + i];
}

// ---------------- GRU: 128 CTAs x 256 threads ------------------------------------
__global__ void k_gru(const float* __restrict__ w_ih, const float* __restrict__ w_hh,
                      const float* __restrict__ b_ih, const float* __restrict__ b_hh) {
    __shared__ __align__(16) float4 sx[EMB / 4];
    __shared__ __align__(16) float4 sh[HID / 4];
    __shared__ float sg[8][3];
    int tid = threadIdx.x;
    if (tid < 128)       sx[tid]       = ((const float4*)g_y)[tid];
    else if (tid < 256)  sh[tid - 128] = ((const float4*)g_h)[tid - 128];
    __syncthreads();

    int wid = tid >> 5, lane = tid & 31;
    int j = blockIdx.x * 4 + (wid & 3);
    bool is_hh = wid >= 4;
    const float*  W  = is_hh ? w_hh : w_ih;
    const float4* sv = is_hh ? sh : sx;

    const float4* wr = (const float4*)(W + (size_t)j * 512);
    const float4* wz = (const float4*)(W + (size_t)(512 + j) * 512);
    const float4* wn = (const float4*)(W + (size_t)(1024 + j) * 512);

    float gr = 0.f, gz = 0.f, gn = 0.f;
#pragma unroll
    for (int i = 0; i < 4; i++) {
        int k = lane + 32 * i;
        float4 x4 = sv[k], a;
        a = wr[k]; gr += a.x * x4.x + a.y * x4.y + a.z * x4.z + a.w * x4.w;
        a = wz[k]; gz += a.x * x4.x + a.y * x4.y + a.z * x4.z + a.w * x4.w;
        a = wn[k]; gn += a.x * x4.x + a.y * x4.y + a.z * x4.z + a.w * x4.w;
    }
#pragma unroll
    for (int o = 16; o > 0; o >>= 1) {
        gr += __shfl_xor_sync(~0u, gr, o);
        gz += __shfl_xor_sync(~0u, gz, o);
        gn += __shfl_xor_sync(~0u, gn, o);
    }
    if (lane == 0) { sg[wid][0] = gr; sg[wid][1] = gz; sg[wid][2] = gn; }
    __syncthreads();

    if (tid < 4) {
        int jj = blockIdx.x * 4 + tid;
        float ar = (sg[tid][0] + b_ih[jj])        + (sg[tid + 4][0] + b_hh[jj]);
        float az = (sg[tid][1] + b_ih[512 + jj])  + (sg[tid + 4][1] + b_hh[512 + jj]);
        float xn =  sg[tid][2] + b_ih[1024 + jj];
        float hn =  sg[tid + 4][2] + b_hh[1024 + jj];
        float r = 1.f / (1.f + expf(-ar));
        float z = 1.f / (1.f + expf(-az));
        float n = tanhf(xn + r * hn);
        g_hnew[jj] = (1.f - z) * n + z * ((const float*)g_h)[jj];
    }
}

// ---------------- fused attention + elect-last finalize: 148 CTAs x 512 ----------
// Scores bounded (GRU hidden in (-1,1)) => exp safe without max subtraction.
__global__ void __launch_bounds__(NT_F, 1)
k_fused_final(const float* __restrict__ enc,   const float* __restrict__ embed,
              const float* __restrict__ w_out, const float* __restrict__ b_out,
              float* __restrict__ attn_out, float* __restrict__ out_logits,
              int step)
{
    __shared__ __align__(16) float4 sh4[128];       // hnew
    __shared__ __align__(16) float  su[16][512];    // per-warp U partials
    __shared__ float  szw[16];
    __shared__ __align__(16) float4 sU4[4][128];    // final: group partials
    __shared__ __align__(16) float  scat[1024];     // final: [summary|hnew]
    __shared__ float  slog[32];
    __shared__ float  szr[NB_F];
    __shared__ float  sZb;
    __shared__ int    sbest;
    __shared__ int    sflag;

    const int tid = threadIdx.x, wid = tid >> 5, lane = tid & 31, cta = blockIdx.x;
    const float scale = 0.04419417382415922f;       // 1/sqrt(512)

    if (tid < 128) sh4[tid] = ((const float4*)g_hnew)[tid];
    __syncthreads();

    int gw = cta * 16 + wid;
    float4 u0 = make_float4(0.f, 0.f, 0.f, 0.f);
    float4 u1 = u0, u2 = u0, u3 = u0;
    float zacc = 0.f;

    for (int t = gw; t < T_ENC; t += NWARPS) {
        const float4* row = (const float4*)(enc + (size_t)t * 1024);
        float s = 0.f;
#pragma unroll
        for (int i = 0; i < 4; i++) {
            int k = lane + 32 * i;
            float4 a = row[k], h = sh4[k];
            s += a.x * h.x + a.y * h.y + a.z * h.z + a.w * h.w;
        }
#pragma unroll
        for (int o = 16; o > 0; o >>= 1) s += __shfl_xor_sync(~0u, s, o);
        float e = expf(s * scale);
        if (lane == 0) attn_out[t] = e;             // unnormalized; /Z later
        zacc += e;
        float4 v;
        v = row[128 + lane]; u0.x += e * v.x; u0.y += e * v.y; u0.z += e * v.z; u0.w += e * v.w;
        v = row[160 + lane]; u1.x += e * v.x; u1.y += e * v.y; u1.z += e * v.z; u1.w += e * v.w;
        v = row[192 + lane]; u2.x += e * v.x; u2.y += e * v.y; u2.z += e * v.z; u2.w += e * v.w;
        v = row[224 + lane]; u3.x += e * v.x; u3.y += e * v.y; u3.z += e * v.z; u3.w += e * v.w;
    }
    ((float4*)&su[wid][4 * lane])[0]       = u0;
    ((float4*)&su[wid][128 + 4 * lane])[0] = u1;
    ((float4*)&su[wid][256 + 4 * lane])[0] = u2;
    ((float4*)&su[wid][384 + 4 * lane])[0] = u3;
    if (lane == 0) szw[wid] = zacc;
    __syncthreads();

    // CTA-level reduce over 16 warps (fixed order), write partials
    {
        float s2 = su[0][tid];
#pragma unroll
        for (int w = 1; w < 16; w++) s2 += su[w][tid];
        g_partU[cta * 512 + tid] = s2;
    }
    if (tid == 0) {
        float s2 = szw[0];
#pragma unroll
        for (int w = 1; w < 16; w++) s2 += szw[w];
        g_partZ[cta] = s2;
    }
    __syncthreads();

    // ---- elect: last CTA to arrive does the finalize; nobody waits ----
    if (tid == 0) {
        __threadfence();                              // release partials
        unsigned old = atomicAdd(&g_count, 1);
        sflag = (old == NB_F - 1);
        if (sflag) { atomicExch(&g_count, 0); __threadfence(); }  // acquire + reset
    }
    __syncthreads();
    if (!sflag) return;

    // ---- finalize (elected CTA only; fixed reduce order => deterministic) ----
    if (tid < NB_F) szr[tid] = g_partZ[tid];
    __syncthreads();
    if (tid == 0) {
        float z = 0.f;
#pragma unroll
        for (int g = 0; g < NB_F; g++) z += szr[g];
        sZb = z; g_Z[step] = z;
    }

    // U reduce: float4 columns; 4 groups of 37 rows (148 = 4*37)
    {
        int c4 = tid & 127, grp = tid >> 7;
        const float4* pu = (const float4*)g_partU;    // [148][128] float4
        float4 acc = make_float4(0.f, 0.f, 0.f, 0.f);
#pragma unroll
        for (int r = 0; r < 37; r++) {
            float4 v = pu[(size_t)(grp * 37 + r) * 128 + c4];
            acc.x += v.x; acc.y += v.y; acc.z += v.z; acc.w += v.w;
        }
        sU4[grp][c4] = acc;
    }
    __syncthreads();
    float Z = sZb;
    if (tid < 128) {
        float4 a = sU4[0][tid], b = sU4[1][tid], c = sU4[2][tid], d = sU4[3][tid];
        float4 u;
        u.x = ((a.x + b.x) + c.x) + d.x;
        u.y = ((a.y + b.y) + c.y) + d.y;
        u.z = ((a.z + b.z) + c.z) + d.z;
        u.w = ((a.w + b.w) + c.w) + d.w;
        u.x /= Z; u.y /= Z; u.z /= Z; u.w /= Z;
        ((float4*)scat)[tid] = u;
    }
    float hn_commit = g_hnew[tid];
    scat[512 + tid] = hn_commit;
    g_h[tid] = hn_commit;                              // commit hidden state
    __syncthreads();

    // logits: 16 warps cover 31 rows (wid, wid+16)
#pragma unroll
    for (int rr = 0; rr < 2; rr++) {
        int rowi = wid + 16 * rr;
        if (rowi < VOCAB) {
            const float4* wp = (const float4*)(w_out + (size_t)rowi * 1024);
            float s = 0.f;
#pragma unroll
            for (int i = 0; i < 8; i++) {
                int k = lane + 32 * i;
                float4 a = wp[k];
                float4 c = ((const float4*)scat)[k];
                s += a.x * c.x + a.y * c.y + a.z * c.z + a.w * c.w;
            }
#pragma unroll
            for (int o = 16; o > 0; o >>= 1) s += __shfl_xor_sync(~0u, s, o);
            if (lane == 0) {
                s += b_out[rowi];
                if (out_logits) out_logits[rowi] = s;
                slog[rowi] = s;
            }
        }
    }
    __syncthreads();
    if (tid == 0) {
        float bv = slog[0]; int bi = 0;
        for (int v = 1; v < VOCAB; v++)
            if (slog[v] > bv) { bv = slog[v]; bi = v; }   // first-max (jnp.argmax)
        g_best[step] = bi; sbest = bi;
    }
    __syncthreads();
    g_y[tid] = embed[(size_t)sbest * EMB + tid];          // feedback embedding
}

// ---------------- normalize attentions by per-step Z ------------------------------
__global__ void k_norm(float* __restrict__ attn) {
    int i = blockIdx.x * 256 + threadIdx.x;
    attn[i] = attn[i] / g_Z[i >> 14];
}

// ---------------- length -----------------------------------------------------------
__global__ void k_len(float* __restrict__ outp) {
    int len = MAX_LEN;
    for (int i = 0; i < MAX_LEN; i++)
        if (g_best[i] == EOS_IDX) { len = i; break; }
    *outp = (float)len;
}

// -----------------------------------------------------------------------------------
extern "C" void kernel_launch(void* const* d_in, const int* in_sizes, int n_in,
                              void* d_out, int out_size) {
    const float* enc   = (const float*)d_in[0];
    const float* embed = (const float*)d_in[2];
    const float* w_ih  = (const float*)d_in[3];
    const float* w_hh  = (const float*)d_in[4];
    const float* b_ih  = (const float*)d_in[5];
    const float* b_hh  = (const float*)d_in[6];
    const float* w_out = (const float*)d_in[7];
    const float* b_out = (const float*)d_in[8];

    float* outF = (float*)d_out;
    const long long N_LOG  = (long long)MAX_LEN * VOCAB;        // 3100
    const long long N_ATTN = (long long)MAX_LEN * T_ENC;        // 1638400

    float* out_logits = outF;
    float* out_len    = nullptr;
    float* out_attn   = nullptr;
    if ((long long)out_size >= N_LOG + 1 + N_ATTN) {            // logits | len | attn
        out_len  = outF + N_LOG;
        out_attn = outF + N_LOG + 1;
    } else if ((long long)out_size >= N_LOG + N_ATTN) {
        out_attn = outF + N_LOG;
    } else if ((long long)out_size == N_ATTN) {
        out_attn = outF;
        out_logits = nullptr;
    }

    float* attn_fallback = nullptr;
    cudaGetSymbolAddress((void**)&attn_fallback, g_attn_scratch);

    k_init<<<1, 512>>>(embed);
    for (int step = 0; step < MAX_LEN; step++) {
        k_gru<<<128, 256>>>(w_ih, w_hh, b_ih, b_hh);
        float* ao = out_attn ? out_attn + (size_t)step * T_ENC : attn_fallback;
        float* lo = out_logits ? out_logits + (size_t)step * VOCAB : nullptr;
        k_fused_final<<<NB_F, NT_F>>>(enc, embed, w_out, b_out, ao, lo, step);
    }
    if (out_attn) k_norm<<<(MAX_LEN * T_ENC) / 256, 256>>>(out_attn);
    if (out_len)  k_len<<<1, 1>>>(out_len);
}

// round 12
// speedup vs baseline: 1.7611x; 1.0221x over previous
#include <cuda_runtime.h>
#include <math.h>

#define HID     512
#define EMB     512
#define VOCAB   31
#define T_ENC   16384
#define MAX_LEN 100
#define EOS_IDX 29

#define NB_F    148                 // fused CTAs (one wave)
#define NT_F    512                 // threads (16 warps)
#define NWARPS  (NB_F * 16)         // 2368 warps

// ---------------- device state -------------------------------------------------
__device__ float    g_h[HID];
__device__ float    g_y[EMB];
__device__ float    g_hnew[HID];
__device__ float    g_partU[NB_F * HID];
__device__ float    g_partZ[NB_F];
__device__ float    g_Z[MAX_LEN];
__device__ int      g_best[MAX_LEN];
__device__ float    g_attn_scratch[T_ENC];
__device__ unsigned g_count = 0;

__device__ __forceinline__ float dot4(float4 a, float4 b) {
    return a.x * b.x + a.y * b.y + a.z * b.z + a.w * b.w;
}

// ---------------- init -----------------------------------------------------------
__global__ void k_init(const float* __restrict__ embed) {
    int i = threadIdx.x;               // 512
    g_h[i] = 0.f;
    g_y[i] = embed[EOS_IDX * EMB + i];
}

// ---------------- GRU: 128 CTAs x 512 threads ------------------------------------
// Warp w handles (output jj = w&3, matrix = (w>>2)&1, K-half = w>>3).
// All 6 weight float4s prefetched before FMAs -> high MLP, latency hidden.
__global__ void __launch_bounds__(512) k_gru(
        const float* __restrict__ w_ih, const float* __restrict__ w_hh,
        const float* __restrict__ b_ih, const float* __restrict__ b_hh) {
    __shared__ __align__(16) float4 sx[EMB / 4];
    __shared__ __align__(16) float4 sh[HID / 4];
    __shared__ float sg[16][3];
    int tid = threadIdx.x;
    if (tid < 128)       sx[tid]       = ((const float4*)g_y)[tid];
    else if (tid < 256)  sh[tid - 128] = ((const float4*)g_h)[tid - 128];
    __syncthreads();

    int wid = tid >> 5, lane = tid & 31;
    int jj  = wid & 3;
    int mat = (wid >> 2) & 1;
    int kh  = wid >> 3;
    int j   = blockIdx.x * 4 + jj;

    const float*  W  = mat ? w_hh : w_ih;
    const float4* sv = (mat ? sh : sx) + kh * 64;
    const float4* wr = (const float4*)W + (size_t)j * 128          + kh * 64;
    const float4* wz = (const float4*)W + (size_t)(512 + j) * 128  + kh * 64;
    const float4* wn = (const float4*)W + (size_t)(1024 + j) * 128 + kh * 64;

    // prefetch everything (independent loads -> front-batched LDG.128)
    float4 ar0 = wr[lane], ar1 = wr[lane + 32];
    float4 az0 = wz[lane], az1 = wz[lane + 32];
    float4 an0 = wn[lane], an1 = wn[lane + 32];
    float4 x0  = sv[lane], x1  = sv[lane + 32];

    float gr = dot4(ar0, x0) + dot4(ar1, x1);
    float gz = dot4(az0, x0) + dot4(az1, x1);
    float gn = dot4(an0, x0) + dot4(an1, x1);
#pragma unroll
    for (int o = 16; o > 0; o >>= 1) {
        gr += __shfl_xor_sync(~0u, gr, o);
        gz += __shfl_xor_sync(~0u, gz, o);
        gn += __shfl_xor_sync(~0u, gn, o);
    }
    if (lane == 0) { sg[wid][0] = gr; sg[wid][1] = gz; sg[wid][2] = gn; }
    __syncthreads();

    if (tid < 4) {
        int jg = blockIdx.x * 4 + tid;
        // ih partials: wids tid, 8+tid ; hh partials: wids 4+tid, 12+tid
        float gxr = sg[tid][0] + sg[8 + tid][0];
        float gxz = sg[tid][1] + sg[8 + tid][1];
        float gxn = sg[tid][2] + sg[8 + tid][2];
        float ghr = sg[4 + tid][0] + sg[12 + tid][0];
        float ghz = sg[4 + tid][1] + sg[12 + tid][1];
        float ghn = sg[4 + tid][2] + sg[12 + tid][2];
        float ar = (gxr + b_ih[jg])        + (ghr + b_hh[jg]);
        float az = (gxz + b_ih[512 + jg])  + (ghz + b_hh[512 + jg]);
        float xn =  gxn + b_ih[1024 + jg];
        float hn =  ghn + b_hh[1024 + jg];
        float r = 1.f / (1.f + expf(-ar));
        float z = 1.f / (1.f + expf(-az));
        float n = tanhf(xn + r * hn);
        g_hnew[jg] = (1.f - z) * n + z * ((const float*)g_h)[jg];
    }
}

// ---------------- fused attention + elect-last finalize: 148 CTAs x 512 ----------
// Scores bounded (GRU hidden in (-1,1)) => exp safe without max subtraction.
__global__ void __launch_bounds__(NT_F, 1)
k_fused_final(const float* __restrict__ enc,   const float* __restrict__ embed,
              const float* __restrict__ w_out, const float* __restrict__ b_out,
              float* __restrict__ attn_out, float* __restrict__ out_logits,
              int step)
{
    __shared__ __align__(16) float4 sh4[128];       // hnew
    __shared__ __align__(16) float  su[16][512];    // per-warp U partials
    __shared__ float  szw[16];
    __shared__ __align__(16) float4 sU4[4][128];    // final: group partials
    __shared__ __align__(16) float  scat[1024];     // final: [summary|hnew]
    __shared__ float  slog[32];
    __shared__ float  szr[NB_F];
    __shared__ float  sZb;
    __shared__ int    sbest;
    __shared__ int    sflag;

    const int tid = threadIdx.x, wid = tid >> 5, lane = tid & 31, cta = blockIdx.x;
    const float scale = 0.04419417382415922f;       // 1/sqrt(512)

    if (tid < 128) sh4[tid] = ((const float4*)g_hnew)[tid];
    __syncthreads();

    int gw = cta * 16 + wid;
    float4 u0 = make_float4(0.f, 0.f, 0.f, 0.f);
    float4 u1 = u0, u2 = u0, u3 = u0;
    float zacc = 0.f;

    for (int t = gw; t < T_ENC; t += NWARPS) {
        const float4* row = (const float4*)(enc + (size_t)t * 1024);
        float s = 0.f;
#pragma unroll
        for (int i = 0; i < 4; i++) {
            int k = lane + 32 * i;
            float4 a = row[k], h = sh4[k];
            s += a.x * h.x + a.y * h.y + a.z * h.z + a.w * h.w;
        }
#pragma unroll
        for (int o = 16; o > 0; o >>= 1) s += __shfl_xor_sync(~0u, s, o);
        float e = expf(s * scale);
        if (lane == 0) attn_out[t] = e;             // unnormalized; /Z later
        zacc += e;
        float4 v;
        v = row[128 + lane]; u0.x += e * v.x; u0.y += e * v.y; u0.z += e * v.z; u0.w += e * v.w;
        v = row[160 + lane]; u1.x += e * v.x; u1.y += e * v.y; u1.z += e * v.z; u1.w += e * v.w;
        v = row[192 + lane]; u2.x += e * v.x; u2.y += e * v.y; u2.z += e * v.z; u2.w += e * v.w;
        v = row[224 + lane]; u3.x += e * v.x; u3.y += e * v.y; u3.z += e * v.z; u3.w += e * v.w;
    }
    ((float4*)&su[wid][4 * lane])[0]       = u0;
    ((float4*)&su[wid][128 + 4 * lane])[0] = u1;
    ((float4*)&su[wid][256 + 4 * lane])[0] = u2;
    ((float4*)&su[wid][384 + 4 * lane])[0] = u3;
    if (lane == 0) szw[wid] = zacc;
    __syncthreads();

    // CTA-level reduce over 16 warps (fixed order), write partials
    {
        float s2 = su[0][tid];
#pragma unroll
        for (int w = 1; w < 16; w++) s2 += su[w][tid];
        g_partU[cta * 512 + tid] = s2;
    }
    if (tid == 0) {
        float s2 = szw[0];
#pragma unroll
        for (int w = 1; w < 16; w++) s2 += szw[w];
        g_partZ[cta] = s2;
    }
    __syncthreads();

    // ---- elect: last CTA to arrive does the finalize; nobody waits ----
    if (tid == 0) {
        __threadfence();                              // release partials
        unsigned old = atomicAdd(&g_count, 1);
        sflag = (old == NB_F - 1);
        if (sflag) { atomicExch(&g_count, 0); __threadfence(); }  // acquire + reset
    }
    __syncthreads();
    if (!sflag) return;

    // ---- finalize (elected CTA only; fixed reduce order => deterministic) ----
    if (tid < NB_F) szr[tid] = g_partZ[tid];
    __syncthreads();
    if (tid == 0) {
        float z = 0.f;
#pragma unroll
        for (int g = 0; g < NB_F; g++) z += szr[g];
        sZb = z; g_Z[step] = z;
    }

    // U reduce: float4 columns; 4 groups of 37 rows (148 = 4*37)
    {
        int c4 = tid & 127, grp = tid >> 7;
        const float4* pu = (const float4*)g_partU;    // [148][128] float4
        float4 acc = make_float4(0.f, 0.f, 0.f, 0.f);
#pragma unroll
        for (int r = 0; r < 37; r++) {
            float4 v = pu[(size_t)(grp * 37 + r) * 128 + c4];
            acc.x += v.x; acc.y += v.y; acc.z += v.z; acc.w += v.w;
        }
        sU4[grp][c4] = acc;
    }
    __syncthreads();
    float Z = sZb;
    if (tid < 128) {
        float4 a = sU4[0][tid], b = sU4[1][tid], c = sU4[2][tid], d = sU4[3][tid];
        float4 u;
        u.x = ((a.x + b.x) + c.x) + d.x;
        u.y = ((a.y + b.y) + c.y) + d.y;
        u.z = ((a.z + b.z) + c.z) + d.z;
        u.w = ((a.w + b.w) + c.w) + d.w;
        u.x /= Z; u.y /= Z; u.z /= Z; u.w /= Z;
        ((float4*)scat)[tid] = u;
    }
    float hn_commit = g_hnew[tid];
    scat[512 + tid] = hn_commit;
    g_h[tid] = hn_commit;                              // commit hidden state
    __syncthreads();

    // logits: 16 warps cover 31 rows (wid, wid+16)
#pragma unroll
    for (int rr = 0; rr < 2; rr++) {
        int rowi = wid + 16 * rr;
        if (rowi < VOCAB) {
            const float4* wp = (const float4*)(w_out + (size_t)rowi * 1024);
            float s = 0.f;
#pragma unroll
            for (int i = 0; i < 8; i++) {
                int k = lane + 32 * i;
                float4 a = wp[k];
                float4 c = ((const float4*)scat)[k];
                s += a.x * c.x + a.y * c.y + a.z * c.z + a.w * c.w;
            }
#pragma unroll
            for (int o = 16; o > 0; o >>= 1) s += __shfl_xor_sync(~0u, s, o);
            if (lane == 0) {
                s += b_out[rowi];
                if (out_logits) out_logits[rowi] = s;
                slog[rowi] = s;
            }
        }
    }
    __syncthreads();
    if (tid == 0) {
        float bv = slog[0]; int bi = 0;
        for (int v = 1; v < VOCAB; v++)
            if (slog[v] > bv) { bv = slog[v]; bi = v; }   // first-max (jnp.argmax)
        g_best[step] = bi; sbest = bi;
    }
    __syncthreads();
    g_y[tid] = embed[(size_t)sbest * EMB + tid];          // feedback embedding
}

// ---------------- normalize attentions by per-step Z ------------------------------
__global__ void k_norm(float* __restrict__ attn) {
    int i = blockIdx.x * 256 + threadIdx.x;
    attn[i] = attn[i] / g_Z[i >> 14];
}

// ---------------- length -----------------------------------------------------------
__global__ void k_len(float* __restrict__ outp) {
    int len = MAX_LEN;
    for (int i = 0; i < MAX_LEN; i++)
        if (g_best[i] == EOS_IDX) { len = i; break; }
    *outp = (float)len;
}

// -----------------------------------------------------------------------------------
extern "C" void kernel_launch(void* const* d_in, const int* in_sizes, int n_in,
                              void* d_out, int out_size) {
    const float* enc   = (const float*)d_in[0];
    const float* embed = (const float*)d_in[2];
    const float* w_ih  = (const float*)d_in[3];
    const float* w_hh  = (const float*)d_in[4];
    const float* b_ih  = (const float*)d_in[5];
    const float* b_hh  = (const float*)d_in[6];
    const float* w_out = (const float*)d_in[7];
    const float* b_out = (const float*)d_in[8];

    float* outF = (float*)d_out;
    const long long N_LOG  = (long long)MAX_LEN * VOCAB;        // 3100
    const long long N_ATTN = (long long)MAX_LEN * T_ENC;        // 1638400

    float* out_logits = outF;
    float* out_len    = nullptr;
    float* out_attn   = nullptr;
    if ((long long)out_size >= N_LOG + 1 + N_ATTN) {            // logits | len | attn
        out_len  = outF + N_LOG;
        out_attn = outF + N_LOG + 1;
    } else if ((long long)out_size >= N_LOG + N_ATTN) {
        out_attn = outF + N_LOG;
    } else if ((long long)out_size == N_ATTN) {
        out_attn = outF;
        out_logits = nullptr;
    }

    float* attn_fallback = nullptr;
    cudaGetSymbolAddress((void**)&attn_fallback, g_attn_scratch);

    k_init<<<1, 512>>>(embed);
    for (int step = 0; step < MAX_LEN; step++) {
        k_gru<<<128, 512>>>(w_ih, w_hh, b_ih, b_hh);
        float* ao = out_attn ? out_attn + (size_t)step * T_ENC : attn_fallback;
        float* lo = out_logits ? out_logits + (size_t)step * VOCAB : nullptr;
        k_fused_final<<<NB_F, NT_F>>>(enc, embed, w_out, b_out, ao, lo, step);
    }
    if (out_attn) k_norm<<<(MAX_LEN * T_ENC) / 256, 256>>>(out_attn);
    if (out_len)  k_len<<<1, 1>>>(out_len);
}

// round 17
// speedup vs baseline: 1.9802x; 1.1244x over previous
#include <cuda_runtime.h>
#include <math.h>

#define HID     512
#define EMB     512
#define VOCAB   31
#define T_ENC   16384
#define MAX_LEN 100
#define EOS_IDX 29

#define NB_F    148                 // step-kernel CTAs (one wave)
#define NT_F    512                 // threads (16 warps)
#define NWARPS  (NB_F * 16)         // 2368 warps
#define NGATE   1536                // 3*HID gate rows

// ---------------- device state -------------------------------------------------
__device__ float    g_h[HID];                 // committed hidden state (h_{s-1})
__device__ float    g_gx[VOCAB * NGATE];      // precomputed W_ih@embed[v] + b_ih
__device__ float    g_gh[2][NGATE];           // double-buffered W_hh @ h (no bias)
__device__ float    g_partU[NB_F * HID];
__device__ float    g_partZ[NB_F];
__device__ float    g_Z[MAX_LEN];
__device__ int      g_best[MAX_LEN];
__device__ float    g_attn_scratch[T_ENC];
__device__ unsigned g_count = 0;

__device__ __forceinline__ float dot4(float4 a, float4 b) {
    return a.x * b.x + a.y * b.y + a.z * b.z + a.w * b.w;
}

// ---------------- init: h=0, gh[0]=0 ---------------------------------------------
__global__ void k_init() {
    int i = threadIdx.x;               // 512
    g_h[i] = 0.f;
    g_gh[0][i] = 0.f;
    g_gh[0][512 + i] = 0.f;
    g_gh[0][1024 + i] = 0.f;
}

// ---------------- gx table: 96 CTAs x 512 threads --------------------------------
// CTA b owns gate rows [16b, 16b+16). Warp w owns row 16b+w, dots vs all 31 embeds.
__global__ void __launch_bounds__(512) k_table(const float* __restrict__ w_ih,
                                               const float* __restrict__ b_ih,
                                               const float* __restrict__ embed) {
    __shared__ __align__(16) float srows[16][512];
    int tid = threadIdx.x, wid = tid >> 5, lane = tid & 31;
    int rbase = blockIdx.x * 16;

    for (int idx = tid; idx < 16 * 512; idx += 512)
        srows[idx >> 9][idx & 511] = w_ih[(size_t)(rbase + (idx >> 9)) * 512 + (idx & 511)];
    __syncthreads();

    int row = rbase + wid;
    const float4* r4 = (const float4*)srows[wid];
    float4 r0 = r4[lane], r1 = r4[lane + 32], r2 = r4[lane + 64], r3 = r4[lane + 96];
    float bias = b_ih[row];

    for (int v = 0; v < VOCAB; v++) {
        const float4* e4 = (const float4*)(embed + (size_t)v * EMB);
        float s = dot4(e4[lane], r0) + dot4(e4[lane + 32], r1)
                + dot4(e4[lane + 64], r2) + dot4(e4[lane + 96], r3);
#pragma unroll
        for (int o = 16; o > 0; o >>= 1) s += __shfl_xor_sync(~0u, s, o);
        if (lane == 0) g_gx[v * NGATE + row] = s + bias;
    }
}

// ---------------- per-step kernel: 148 CTAs x 512 threads -------------------------
// prologue: redundant GRU combine (gx table + gh buffer) -> h in smem
// mainloop: fused scores+exp+Z+sum(e*v)   (scores bounded, no max pass)
// + embedded W_hh GEMV for NEXT step's gh (warps 0..10)
// epilogue: elect-last CTA finalizes (Z, summary, logits, argmax, commit h/best)
__global__ void __launch_bounds__(NT_F, 1)
k_step(const float* __restrict__ enc,   const float* __restrict__ w_hh,
       const float* __restrict__ b_hh,  const float* __restrict__ w_out,
       const float* __restrict__ b_out, float* __restrict__ attn_out,
       float* __restrict__ out_logits,  int step)
{
    __shared__ __align__(16) float4 sh4[128];       // h_s
    __shared__ __align__(16) float  su[16][512];    // per-warp U partials
    __shared__ float  szw[16];
    __shared__ __align__(16) float4 sU4[4][128];    // final: group partials
    __shared__ __align__(16) float  scat[1024];     // final: [summary|h]
    __shared__ float  slog[32];
    __shared__ float  szr[NB_F];
    __shared__ float  sZb;
    __shared__ int    sbest;
    __shared__ int    sflag;

    const int tid = threadIdx.x, wid = tid >> 5, lane = tid & 31, cta = blockIdx.x;
    const float scale = 0.04419417382415922f;       // 1/sqrt(512)
    const int par = step & 1;

    // ---- GRU combine (redundant in every CTA; deterministic) ----
    {
        int bp = (step == 0) ? EOS_IDX : g_best[step - 1];
        const float* gx = g_gx + (size_t)bp * NGATE;
        const float* gh = g_gh[par];
        float gxr = gx[tid], gxz = gx[512 + tid], gxn = gx[1024 + tid];
        float ghr = gh[tid]        + b_hh[tid];
        float ghz = gh[512 + tid]  + b_hh[512 + tid];
        float ghn = gh[1024 + tid] + b_hh[1024 + tid];
        float r = 1.f / (1.f + expf(-(gxr + ghr)));
        float z = 1.f / (1.f + expf(-(gxz + ghz)));
        float n = tanhf(gxn + r * ghn);
        float h = (1.f - z) * n + z * g_h[tid];
        ((float*)sh4)[tid] = h;
    }
    __syncthreads();

    // ---- attention mainloop ----
    int gw = cta * 16 + wid;
    float4 u0 = make_float4(0.f, 0.f, 0.f, 0.f);
    float4 u1 = u0, u2 = u0, u3 = u0;
    float zacc = 0.f;

    for (int t = gw; t < T_ENC; t += NWARPS) {
        const float4* row = (const float4*)(enc + (size_t)t * 1024);
        float s = 0.f;
#pragma unroll
        for (int i = 0; i < 4; i++) {
            int k = lane + 32 * i;
            float4 a = row[k], h = sh4[k];
            s += a.x * h.x + a.y * h.y + a.z * h.z + a.w * h.w;
        }
#pragma unroll
        for (int o = 16; o > 0; o >>= 1) s += __shfl_xor_sync(~0u, s, o);
        float e = expf(s * scale);
        if (lane == 0) attn_out[t] = e;             // unnormalized; /Z later
        zacc += e;
        float4 v;
        v = row[128 + lane]; u0.x += e * v.x; u0.y += e * v.y; u0.z += e * v.z; u0.w += e * v.w;
        v = row[160 + lane]; u1.x += e * v.x; u1.y += e * v.y; u1.z += e * v.z; u1.w += e * v.w;
        v = row[192 + lane]; u2.x += e * v.x; u2.y += e * v.y; u2.z += e * v.z; u2.w += e * v.w;
        v = row[224 + lane]; u3.x += e * v.x; u3.y += e * v.y; u3.z += e * v.z; u3.w += e * v.w;
    }
    ((float4*)&su[wid][4 * lane])[0]       = u0;
    ((float4*)&su[wid][128 + 4 * lane])[0] = u1;
    ((float4*)&su[wid][256 + 4 * lane])[0] = u2;
    ((float4*)&su[wid][384 + 4 * lane])[0] = u3;
    if (lane == 0) szw[wid] = zacc;

    // ---- embedded W_hh GEMV for NEXT step: gh' = W_hh @ h_s ----
    {
        int grow = cta + 148 * wid;                 // warps 0..10 get a row
        if (grow < NGATE) {
            const float4* wr = (const float4*)w_hh + (size_t)grow * 128;
            float s = dot4(wr[lane],      sh4[lane])
                    + dot4(wr[lane + 32], sh4[lane + 32])
                    + dot4(wr[lane + 64], sh4[lane + 64])
                    + dot4(wr[lane + 96], sh4[lane + 96]);
#pragma unroll
            for (int o = 16; o > 0; o >>= 1) s += __shfl_xor_sync(~0u, s, o);
            if (lane == 0) g_gh[par ^ 1][grow] = s;
        }
    }
    __syncthreads();

    // ---- CTA reduce over 16 warps (fixed order), write partials ----
    {
        float s2 = su[0][tid];
#pragma unroll
        for (int w = 1; w < 16; w++) s2 += su[w][tid];
        g_partU[cta * 512 + tid] = s2;
    }
    if (tid == 0) {
        float s2 = szw[0];
#pragma unroll
        for (int w = 1; w < 16; w++) s2 += szw[w];
        g_partZ[cta] = s2;
    }
    __syncthreads();

    // ---- elect: last CTA to arrive finalizes; nobody waits ----
    if (tid == 0) {
        __threadfence();                              // release partials
        unsigned old = atomicAdd(&g_count, 1);
        sflag = (old == NB_F - 1);
        if (sflag) { atomicExch(&g_count, 0); __threadfence(); }  // acquire + reset
    }
    __syncthreads();
    if (!sflag) return;

    // ---- finalize (elected CTA only; fixed reduce order => deterministic) ----
    if (tid < NB_F) szr[tid] = g_partZ[tid];
    __syncthreads();
    if (tid == 0) {
        float z = 0.f;
#pragma unroll
        for (int g = 0; g < NB_F; g++) z += szr[g];
        sZb = z; g_Z[step] = z;
    }

    // U reduce: float4 columns; 4 groups of 37 rows (148 = 4*37)
    {
        int c4 = tid & 127, grp = tid >> 7;
        const float4* pu = (const float4*)g_partU;    // [148][128] float4
        float4 acc = make_float4(0.f, 0.f, 0.f, 0.f);
#pragma unroll
        for (int r = 0; r < 37; r++) {
            float4 v = pu[(size_t)(grp * 37 + r) * 128 + c4];
            acc.x += v.x; acc.y += v.y; acc.z += v.z; acc.w += v.w;
        }
        sU4[grp][c4] = acc;
    }
    __syncthreads();
    float Z = sZb;
    if (tid < 128) {
        float4 a = sU4[0][tid], b = sU4[1][tid], c = sU4[2][tid], d = sU4[3][tid];
        float4 u;
        u.x = (((a.x + b.x) + c.x) + d.x) / Z;
        u.y = (((a.y + b.y) + c.y) + d.y) / Z;
        u.z = (((a.z + b.z) + c.z) + d.z) / Z;
        u.w = (((a.w + b.w) + c.w) + d.w) / Z;
        ((float4*)scat)[tid] = u;
    }
    {
        float h = ((const float*)sh4)[tid];
        scat[512 + tid] = h;
        g_h[tid] = h;                                  // commit hidden state
    }
    __syncthreads();

    // logits: 16 warps cover 31 rows (wid, wid+16)
#pragma unroll
    for (int rr = 0; rr < 2; rr++) {
        int rowi = wid + 16 * rr;
        if (rowi < VOCAB) {
            const float4* wp = (const float4*)(w_out + (size_t)rowi * 1024);
            float s = 0.f;
#pragma unroll
            for (int i = 0; i < 8; i++) {
                int k = lane + 32 * i;
                float4 a = wp[k];
                float4 c = ((const float4*)scat)[k];
                s += a.x * c.x + a.y * c.y + a.z * c.z + a.w * c.w;
            }
#pragma unroll
            for (int o = 16; o > 0; o >>= 1) s += __shfl_xor_sync(~0u, s, o);
            if (lane == 0) {
                s += b_out[rowi];
                if (out_logits) out_logits[rowi] = s;
                slog[rowi] = s;
            }
        }
    }
    __syncthreads();
    if (tid == 0) {
        float bv = slog[0]; int bi = 0;
        for (int v = 1; v < VOCAB; v++)
            if (slog[v] > bv) { bv = slog[v]; bi = v; }   // first-max (jnp.argmax)
        g_best[step] = bi;
    }
}

// ---------------- normalize attentions by per-step Z ------------------------------
__global__ void k_norm(float* __restrict__ attn) {
    int i = blockIdx.x * 256 + threadIdx.x;
    attn[i] = attn[i] / g_Z[i >> 14];
}

// ---------------- length -----------------------------------------------------------
__global__ void k_len(float* __restrict__ outp) {
    int len = MAX_LEN;
    for (int i = 0; i < MAX_LEN; i++)
        if (g_best[i] == EOS_IDX) { len = i; break; }
    *outp = (float)len;
}

// -----------------------------------------------------------------------------------
extern "C" void kernel_launch(void* const* d_in, const int* in_sizes, int n_in,
                              void* d_out, int out_size) {
    const float* enc   = (const float*)d_in[0];
    const float* embed = (const float*)d_in[2];
    const float* w_ih  = (const float*)d_in[3];
    const float* w_hh  = (const float*)d_in[4];
    const float* b_ih  = (const float*)d_in[5];
    const float* b_hh  = (const float*)d_in[6];
    const float* w_out = (const float*)d_in[7];
    const float* b_out = (const float*)d_in[8];

    float* outF = (float*)d_out;
    const long long N_LOG  = (long long)MAX_LEN * VOCAB;        // 3100
    const long long N_ATTN = (long long)MAX_LEN * T_ENC;        // 1638400

    float* out_logits = outF;
    float* out_len    = nullptr;
    float* out_attn   = nullptr;
    if ((long long)out_size >= N_LOG + 1 + N_ATTN) {            // logits | len | attn
        out_len  = outF + N_LOG;
        out_attn = outF + N_LOG + 1;
    } else if ((long long)out_size >= N_LOG + N_ATTN) {
        out_attn = outF + N_LOG;
    } else if ((long long)out_size == N_ATTN) {
        out_attn = outF;
        out_logits = nullptr;
    }

    float* attn_fallback = nullptr;
    cudaGetSymbolAddress((void**)&attn_fallback, g_attn_scratch);

    k_init<<<1, 512>>>();
    k_table<<<96, 512>>>(w_ih, b_ih, embed);
    for (int step = 0; step < MAX_LEN; step++) {
        float* ao = out_attn ? out_attn + (size_t)step * T_ENC : attn_fallback;
        float* lo = out_logits ? out_logits + (size_t)step * VOCAB : nullptr;
        k_step<<<NB_F, NT_F>>>(enc, w_hh, b_hh, w_out, b_out, ao, lo, step);
    }
    if (out_attn) k_norm<<<(MAX_LEN * T_ENC) / 256, 256>>>(out_attn);
    if (out_len)  k_len<<<1, 1>>>(out_len);
}